// round 5
// baseline (speedup 1.0000x reference)
#include <cuda_runtime.h>
#include <cuda_bf16.h>
#include <cstdint>

#define S_TOK 16384
#define D_DIM 4096
#define N_EXP 64
#define CAP   320
#define KC    64                 // K elements per chunk
#define NCHUNK (D_DIM / KC)      // 64
#define BM    128

#define SWZ(o) ((o) ^ (((o) >> 3) & 0x70))

// ---------------- scratch (static device globals) ----------------
__device__ float g_logits[S_TOK * N_EXP];
// W bf16 hi/lo tiles: [chunk][expert][36 words] (rows padded 128B->144B for
// conflict-free B-fragment LDS: stride 36 words == 4 mod 32 banks)
__device__ __align__(16) uint32_t g_whT[NCHUNK * 64 * 36];
__device__ __align__(16) uint32_t g_wlT[NCHUNK * 64 * 36];
__device__ int   g_e1[S_TOK];
__device__ int   g_e2[S_TOK];
__device__ int   g_want2[S_TOK];
__device__ float g_g1n[S_TOK];
__device__ float g_g2n[S_TOK];
__device__ int   g_bc1[64][64];
__device__ int   g_bc2[64][64];
__device__ int   g_base1[64][64];
__device__ int   g_base2[64][64];
__device__ int   g_cap2[64];
__device__ int   g_nflag;
__device__ int   g_flagged[S_TOK];

// ---------------- PTX helpers (sm_80-portable only) ----------------
__device__ __forceinline__ uint32_t smem_to_u32(const void* p) {
    uint32_t a;
    asm("{ .reg .u64 t; cvta.to.shared.u64 t, %1; cvt.u32.u64 %0, t; }" : "=r"(a) : "l"(p));
    return a;
}
#define CP_ASYNC16(dst, src) \
    asm volatile("cp.async.cg.shared.global [%0], [%1], 16;" :: "r"(dst), "l"(src) : "memory")
#define CP_ASYNC_COMMIT()  asm volatile("cp.async.commit_group;" ::: "memory")
#define CP_ASYNC_WAIT0()   asm volatile("cp.async.wait_group 0;" ::: "memory")

#define LDSM_X4(r0, r1, r2, r3, addr) \
    asm volatile("ldmatrix.sync.aligned.m8n8.x4.shared.b16 {%0,%1,%2,%3}, [%4];" \
        : "=r"(r0), "=r"(r1), "=r"(r2), "=r"(r3) : "r"(addr))

#define LDS32(r, addr) \
    asm volatile("ld.shared.b32 %0, [%1];" : "=r"(r) : "r"(addr))

#define STS32(addr, v) \
    asm volatile("st.shared.b32 [%0], %1;" :: "r"(addr), "r"(v) : "memory")

#define MMA_BF16(d, a, b0, b1) \
    asm volatile("mma.sync.aligned.m16n8k16.row.col.f32.bf16.bf16.f32 " \
        "{%0,%1,%2,%3}, {%4,%5,%6,%7}, {%8,%9}, {%0,%1,%2,%3};" \
        : "+f"((d)[0]), "+f"((d)[1]), "+f"((d)[2]), "+f"((d)[3]) \
        : "r"((a)[0]), "r"((a)[1]), "r"((a)[2]), "r"((a)[3]), "r"(b0), "r"(b1))

// smem layout for gemm (dynamic)
#define XH(s) (sb + (s) * 16384)
#define XL(s) (sb + 32768 + (s) * 16384)
#define WHS(s) (sb + 65536 + (s) * 9216)
#define WLS(s) (sb + 83968 + (s) * 9216)
#define SMEM_TOTAL 102400

// ---------------- zero fill ----------------
__global__ void zero_kernel(float4* __restrict__ out) {
    if (blockIdx.x == 0 && threadIdx.x == 0) g_nflag = 0;
    out[blockIdx.x * 256 + threadIdx.x] = make_float4(0.f, 0.f, 0.f, 0.f);
}

// ---------------- W pre-conversion: fp32 -> bf16 hi/lo padded tiles ----------------
__global__ __launch_bounds__(256)
void wconv_kernel(const float* __restrict__ W) {
    const int pid = blockIdx.x * 256 + threadIdx.x;   // 0..131071
    const int n = pid >> 11;                          // expert 0..63
    const int j = pid & 2047;                         // k-pair 0..2047
    const int k = j * 2;
    const float2 v = *(const float2*)(W + (size_t)n * D_DIM + k);
    const __nv_bfloat16 h0 = __float2bfloat16_rn(v.x);
    const __nv_bfloat16 h1 = __float2bfloat16_rn(v.y);
    const float r0 = v.x - __bfloat162float(h0);
    const float r1 = v.y - __bfloat162float(h1);
    const __nv_bfloat16 l0 = __float2bfloat16_rn(r0);
    const __nv_bfloat16 l1 = __float2bfloat16_rn(r1);
    const uint32_t hp = (uint32_t)__bfloat16_as_ushort(h0) | ((uint32_t)__bfloat16_as_ushort(h1) << 16);
    const uint32_t lp = (uint32_t)__bfloat16_as_ushort(l0) | ((uint32_t)__bfloat16_as_ushort(l1) << 16);
    const int chunk = j >> 5;          // k/64
    const int kw    = j & 31;          // word within row
    const int idx = chunk * 2304 + n * 36 + kw;
    g_whT[idx] = hp;
    g_wlT[idx] = lp;
}

// ---------------- HMMA GEMM: logits = X @ W^T via bf16 split-3 ----------------
__global__ __launch_bounds__(256, 1)
void gemm_mma(const float* __restrict__ X) {
    extern __shared__ __align__(128) char smem[];
    const uint32_t sb = smem_to_u32(smem);
    const int tid = threadIdx.x, wid = tid >> 5, lane = tid & 31;
    const int m0 = blockIdx.x * BM;

    float acc[8][4];
#pragma unroll
    for (int n = 0; n < 8; ++n)
#pragma unroll
        for (int q = 0; q < 4; ++q) acc[n][q] = 0.f;

    const float* xbase = X + (size_t)(m0 + wid) * D_DIM + lane * 2;
    const uint32_t a_log = (uint32_t)((wid * 16 + (lane & 15)) * 128 + (lane >> 4) * 16);
    const uint32_t b_off = (uint32_t)((lane >> 2) * 144 + (lane & 3) * 4);

    float2 v[16];
    auto loadx = [&](int c, float2* vv) {
        const float* p = xbase + c * KC;
#pragma unroll
        for (int jj = 0; jj < 16; ++jj)
            vv[jj] = *(const float2*)(p + (size_t)(jj * 8) * D_DIM);
    };
    auto storeA = [&](int s, const float2* vv) {
        const uint32_t xh = XH(s), xl = XL(s);
#pragma unroll
        for (int jj = 0; jj < 16; ++jj) {
            const int row = wid + jj * 8;
            const float f0 = vv[jj].x, f1 = vv[jj].y;
            const __nv_bfloat16 h0 = __float2bfloat16_rn(f0);
            const __nv_bfloat16 h1 = __float2bfloat16_rn(f1);
            const float r0 = f0 - __bfloat162float(h0);
            const float r1 = f1 - __bfloat162float(h1);
            const __nv_bfloat16 l0 = __float2bfloat16_rn(r0);
            const __nv_bfloat16 l1 = __float2bfloat16_rn(r1);
            const uint32_t hp = (uint32_t)__bfloat16_as_ushort(h0) | ((uint32_t)__bfloat16_as_ushort(h1) << 16);
            const uint32_t lp = (uint32_t)__bfloat16_as_ushort(l0) | ((uint32_t)__bfloat16_as_ushort(l1) << 16);
            const uint32_t off = SWZ((uint32_t)(row * 128 + lane * 4));
            STS32(xh + off, hp);
            STS32(xl + off, lp);
        }
    };
    auto loadB = [&](int c, int s) {
        const uint32_t wh = WHS(s), wl = WLS(s);
        const char* gh = (const char*)(g_whT + c * 2304);
        const char* gl = (const char*)(g_wlT + c * 2304);
        for (int i = tid; i < 576; i += 256) {
            CP_ASYNC16(wh + i * 16, gh + i * 16);
            CP_ASYNC16(wl + i * 16, gl + i * 16);
        }
    };

    // prologue: chunk 0
    loadB(0, 0);
    CP_ASYNC_COMMIT();
    loadx(0, v);
    storeA(0, v);
    CP_ASYNC_WAIT0();
    __syncthreads();

    for (int c = 0; c < NCHUNK; ++c) {
        const int s = c & 1;
        float2 nv[16];
        if (c + 1 < NCHUNK) {
            loadB(c + 1, s ^ 1);
            CP_ASYNC_COMMIT();
            loadx(c + 1, nv);
        }
        const uint32_t xh = XH(s), xl = XL(s), wh = WHS(s), wl = WLS(s);
#pragma unroll
        for (int ks = 0; ks < 4; ++ks) {
            uint32_t ah[4], al[4];
            const uint32_t lg = a_log + ks * 32;
            LDSM_X4(ah[0], ah[1], ah[2], ah[3], xh + SWZ(lg));
            LDSM_X4(al[0], al[1], al[2], al[3], xl + SWZ(lg));

            // preload all B fragments for this k-step into registers
            uint32_t bh[16], bl[16];
#pragma unroll
            for (int nt = 0; nt < 8; ++nt) {
                const uint32_t bo = (uint32_t)(nt * 1152 + ks * 32) + b_off;
                LDS32(bh[nt * 2],     wh + bo);
                LDS32(bh[nt * 2 + 1], wh + bo + 16);
                LDS32(bl[nt * 2],     wl + bo);
                LDS32(bl[nt * 2 + 1], wl + bo + 16);
            }
            // product-major MMA bursts: dependency distance 8 -> fully pipelined
#pragma unroll
            for (int nt = 0; nt < 8; ++nt)
                MMA_BF16(acc[nt], ah, bh[nt * 2], bh[nt * 2 + 1]);
#pragma unroll
            for (int nt = 0; nt < 8; ++nt)
                MMA_BF16(acc[nt], al, bh[nt * 2], bh[nt * 2 + 1]);
#pragma unroll
            for (int nt = 0; nt < 8; ++nt)
                MMA_BF16(acc[nt], ah, bl[nt * 2], bl[nt * 2 + 1]);
        }
        if (c + 1 < NCHUNK) storeA(s ^ 1, nv);
        CP_ASYNC_WAIT0();
        __syncthreads();
    }

    // epilogue: d0,d1 -> row g, cols 2j,2j+1; d2,d3 -> row g+8
    const int r0 = m0 + wid * 16 + (lane >> 2);
    const int cb = 2 * (lane & 3);
#pragma unroll
    for (int nt = 0; nt < 8; ++nt) {
        const int col = nt * 8 + cb;
        *(float2*)&g_logits[(size_t)r0 * 64 + col]       = make_float2(acc[nt][0], acc[nt][1]);
        *(float2*)&g_logits[(size_t)(r0 + 8) * 64 + col] = make_float2(acc[nt][2], acc[nt][3]);
    }
}

// ---------------- Threefry-2x32 (JAX partitionable, key(1)) ----------------
__device__ __forceinline__ void threefry2x32(uint32_t x0, uint32_t x1,
                                             uint32_t& o0, uint32_t& o1) {
    const uint32_t k0 = 0u, k1 = 1u, k2 = 0x1BD11BDBu;
    x0 += k0; x1 += k1;
#define TFR(r) { x0 += x1; x1 = (x1 << (r)) | (x1 >> (32 - (r))); x1 ^= x0; }
    TFR(13) TFR(15) TFR(26) TFR(6)  x0 += k1; x1 += k2 + 1u;
    TFR(17) TFR(29) TFR(16) TFR(24) x0 += k2; x1 += k0 + 2u;
    TFR(13) TFR(15) TFR(26) TFR(6)  x0 += k0; x1 += k1 + 3u;
    TFR(17) TFR(29) TFR(16) TFR(24) x0 += k1; x1 += k2 + 4u;
    TFR(13) TFR(15) TFR(26) TFR(6)  x0 += k2; x1 += k0 + 5u;
#undef TFR
    o0 = x0; o1 = x1;
}
__device__ __forceinline__ float jax_uniform_partitionable(uint32_t i) {
    uint32_t o0, o1;
    threefry2x32(0u, i, o0, o1);
    const uint32_t bits = o0 ^ o1;
    return __uint_as_float((bits >> 9) | 0x3f800000u) - 1.0f;
}

// ---------------- softmax + top2 + stochastic want2 + margin flagging ----------------
__global__ __launch_bounds__(256)
void topk_kernel() {
    const int warp = threadIdx.x >> 5;
    const int lane = threadIdx.x & 31;
    const int i    = blockIdx.x * 8 + warp;

    const float l0 = g_logits[(size_t)i * 64 + lane];
    const float l1 = g_logits[(size_t)i * 64 + 32 + lane];
    const float NEG_INF = __int_as_float(0xff800000);

    // top-1
    float v; int idx;
    if (l1 > l0) { v = l1; idx = lane + 32; } else { v = l0; idx = lane; }
#pragma unroll
    for (int off = 16; off; off >>= 1) {
        float ov = __shfl_xor_sync(0xffffffffu, v, off);
        int   oi = __shfl_xor_sync(0xffffffffu, idx, off);
        if (ov > v || (ov == v && oi < idx)) { v = ov; idx = oi; }
    }
    const float m = v; const int i1 = idx;

    // top-2
    float w0 = (lane == i1) ? NEG_INF : l0;
    float w1 = (lane + 32 == i1) ? NEG_INF : l1;
    float v2; int idx2;
    if (w1 > w0) { v2 = w1; idx2 = lane + 32; } else { v2 = w0; idx2 = lane; }
#pragma unroll
    for (int off = 16; off; off >>= 1) {
        float ov = __shfl_xor_sync(0xffffffffu, v2, off);
        int   oi = __shfl_xor_sync(0xffffffffu, idx2, off);
        if (ov > v2 || (ov == v2 && oi < idx2)) { v2 = ov; idx2 = oi; }
    }

    // top-3 value (for margin check only)
    float u0 = (lane == i1 || lane == idx2) ? NEG_INF : l0;
    float u1 = (lane + 32 == i1 || lane + 32 == idx2) ? NEG_INF : l1;
    float v3 = (u1 > u0) ? u1 : u0;
#pragma unroll
    for (int off = 16; off; off >>= 1) {
        float ov = __shfl_xor_sync(0xffffffffu, v3, off);
        if (ov > v3) v3 = ov;
    }

    float s = expf(l0 - m) + expf(l1 - m);
#pragma unroll
    for (int off = 16; off; off >>= 1)
        s += __shfl_xor_sync(0xffffffffu, s, off);

    if (lane == 0) {
        const float g1 = 1.0f / s;
        const float g2 = expf(v2 - m) / s;
        const float denom = g1 + g2;
        const float g1n = g1 / denom;
        const float g2n = g2 / denom;
        const float rnd = jax_uniform_partitionable((uint32_t)i);
        g_e1[i] = i1;
        g_e2[i] = idx2;
        g_g1n[i] = g1n;
        g_g2n[i] = g2n;
        g_want2[i] = (rnd < 2.0f * g2n) ? 1 : 0;

        const float TAU = 1e-4f;
        if ((m - v2) < TAU || (v2 - v3) < TAU || fabsf(rnd - 2.0f * g2n) < TAU) {
            const int k = atomicAdd(&g_nflag, 1);
            g_flagged[k] = i;
        }
    }
}

// ---------------- exact fp32 rescue for margin-flagged tokens ----------------
__global__ __launch_bounds__(256)
void rescue_kernel(const float* __restrict__ X, const float* __restrict__ W) {
    __shared__ float part[64][4];
    __shared__ float lg[64];
    const int t = threadIdx.x;
    const int e = t >> 2, p = t & 3;
    const int nf = g_nflag;

    for (int fi = blockIdx.x; fi < nf; fi += gridDim.x) {
        const int i = g_flagged[fi];
        const float4* xr = (const float4*)(X + (size_t)i * D_DIM + p * 1024);
        const float4* wr = (const float4*)(W + (size_t)e * D_DIM + p * 1024);
        float a0 = 0.f, a1 = 0.f, a2 = 0.f, a3 = 0.f;
        for (int j = 0; j < 256; ++j) {
            const float4 xa = xr[j];
            const float4 wa = wr[j];
            a0 = fmaf(xa.x, wa.x, a0);
            a1 = fmaf(xa.y, wa.y, a1);
            a2 = fmaf(xa.z, wa.z, a2);
            a3 = fmaf(xa.w, wa.w, a3);
        }
        part[e][p] = ((a0 + a1) + a2) + a3;
        __syncthreads();
        if (t < 64)
            lg[t] = ((part[t][0] + part[t][1]) + part[t][2]) + part[t][3];
        __syncthreads();

        if (t < 32) {
            const int lane = t;
            const float l0 = lg[lane];
            const float l1 = lg[lane + 32];
            const float NEG_INF = __int_as_float(0xff800000);

            float v; int idx;
            if (l1 > l0) { v = l1; idx = lane + 32; } else { v = l0; idx = lane; }
#pragma unroll
            for (int off = 16; off; off >>= 1) {
                float ov = __shfl_xor_sync(0xffffffffu, v, off);
                int   oi = __shfl_xor_sync(0xffffffffu, idx, off);
                if (ov > v || (ov == v && oi < idx)) { v = ov; idx = oi; }
            }
            const float mm = v; const int i1 = idx;

            float w0 = (lane == i1) ? NEG_INF : l0;
            float w1 = (lane + 32 == i1) ? NEG_INF : l1;
            float v2; int idx2;
            if (w1 > w0) { v2 = w1; idx2 = lane + 32; } else { v2 = w0; idx2 = lane; }
#pragma unroll
            for (int off = 16; off; off >>= 1) {
                float ov = __shfl_xor_sync(0xffffffffu, v2, off);
                int   oi = __shfl_xor_sync(0xffffffffu, idx2, off);
                if (ov > v2 || (ov == v2 && oi < idx2)) { v2 = ov; idx2 = oi; }
            }

            float s = expf(l0 - mm) + expf(l1 - mm);
#pragma unroll
            for (int off = 16; off; off >>= 1)
                s += __shfl_xor_sync(0xffffffffu, s, off);

            if (lane == 0) {
                const float g1 = 1.0f / s;
                const float g2 = expf(v2 - mm) / s;
                const float denom = g1 + g2;
                g_e1[i] = i1;
                g_e2[i] = idx2;
                g_g1n[i] = g1 / denom;
                g_g2n[i] = g2 / denom;
                const float rnd = jax_uniform_partitionable((uint32_t)i);
                g_want2[i] = (rnd < 2.0f * (g2 / denom)) ? 1 : 0;
            }
        }
        __syncthreads();
    }
}

// ---------------- per-block expert histograms ----------------
__global__ __launch_bounds__(256)
void hist_kernel() {
    __shared__ int c1[64], c2[64];
    const int t = threadIdx.x;
    if (t < 64) { c1[t] = 0; c2[t] = 0; }
    __syncthreads();
    const int i = blockIdx.x * 256 + t;
    atomicAdd(&c1[g_e1[i]], 1);
    if (g_want2[i]) atomicAdd(&c2[g_e2[i]], 1);
    __syncthreads();
    if (t < 64) { g_bc1[blockIdx.x][t] = c1[t]; g_bc2[blockIdx.x][t] = c2[t]; }
}

// ---------------- cross-block scan ----------------
__global__ void scan_kernel() {
    const int e = threadIdx.x;
    if (e >= 64) return;
    int r1 = 0, r2 = 0;
    for (int b = 0; b < 64; ++b) {
        g_base1[b][e] = r1; r1 += g_bc1[b][e];
        g_base2[b][e] = r2; r2 += g_bc2[b][e];
    }
    const int counts1 = r1 < CAP ? r1 : CAP;
    g_cap2[e] = CAP - counts1;
}

// ---------------- final ranks + scatter ----------------
__global__ __launch_bounds__(256)
void assign_kernel(float* __restrict__ out) {
    __shared__ int wc1[8][64];
    __shared__ int wc2[8][64];
    const int t = threadIdx.x, warp = t >> 5, lane = t & 31;

    ((int*)wc1)[t] = 0; ((int*)wc1)[t + 256] = 0;
    ((int*)wc2)[t] = 0; ((int*)wc2)[t + 256] = 0;
    __syncthreads();

    const int i  = blockIdx.x * 256 + t;
    const int e1 = g_e1[i], e2 = g_e2[i], want2 = g_want2[i];
    const unsigned lt = (1u << lane) - 1u;

    const unsigned m1 = __match_any_sync(0xffffffffu, e1);
    const int lr1 = __popc(m1 & lt);
    if (lr1 == 0) wc1[warp][e1] = __popc(m1);

    const unsigned act2 = __ballot_sync(0xffffffffu, want2);
    const unsigned m2 = __match_any_sync(0xffffffffu, e2) & act2;
    const int lr2 = __popc(m2 & lt);
    if (want2 && lr2 == 0) wc2[warp][e2] = __popc(m2);
    __syncthreads();

    int off1 = 0, off2 = 0;
    for (int w = 0; w < warp; ++w) {
        off1 += wc1[w][e1];
        off2 += wc2[w][e2];
    }

    const int pos1 = g_base1[blockIdx.x][e1] + off1 + lr1 + 1;
    if (pos1 <= CAP) out[(size_t)i * 64 + e1] = g_g1n[i];
    if (want2) {
        const int pos2 = g_base2[blockIdx.x][e2] + off2 + lr2 + 1;
        if (pos2 <= g_cap2[e2]) out[(size_t)i * 64 + e2] = g_g2n[i];
    }
}

// ---------------- launcher ----------------
extern "C" void kernel_launch(void* const* d_in, const int* in_sizes, int n_in,
                              void* d_out, int out_size) {
    const float* x = (const float*)d_in[0];
    const float* w = (const float*)d_in[1];
    float* out = (float*)d_out;

    cudaFuncSetAttribute(gemm_mma, cudaFuncAttributeMaxDynamicSharedMemorySize, SMEM_TOTAL);

    zero_kernel<<<(S_TOK * N_EXP) / (256 * 4), 256>>>((float4*)out);
    wconv_kernel<<<512, 256>>>(w);
    gemm_mma<<<S_TOK / BM, 256, SMEM_TOTAL>>>(x);
    topk_kernel<<<S_TOK / 8, 256>>>();
    rescue_kernel<<<64, 256>>>(x, w);
    hist_kernel<<<S_TOK / 256, 256>>>();
    scan_kernel<<<1, 64>>>();
    assign_kernel<<<S_TOK / 256, 256>>>(out);
}